// round 14
// baseline (speedup 1.0000x reference)
#include <cuda_runtime.h>
#include <cuda_bf16.h>

// ---------------- problem constants ----------------
#define BB 4
#define CC 64
#define PP 16384
#define NM 256      // 16x16 modes, mode = k_idx*16 + m_idx, k = k_idx-8, m = m_idx-8
#define NCAN 144    // canonical modes (Hermitian-reduced)
#define EMB 256
#define HID 64

// Canonical layout: j = r*16 + t, r in 0..8
//  r=0        : (k_idx=0,    m_idx=t)
//  r=1..7     : (k_idx=8+r,  m_idx=t)
//  r=8, t<7   : (k_idx=1+t,  m_idx=0)
//  r=8, t==7  : (k_idx=8,    m_idx=0)
//  r=8, t>=8  : (k_idx=8,    m_idx=t)

// ---------------- device scratch ----------------
__device__ float2 g_xhat [BB*NM*CC];     // only first BB*NCAN*CC used, [b][j][c]
__device__ float2 g_xhat2[BB*NM*CC];     // full 256 modes, [b][mode][c]
__device__ float2 g_wT   [NM*CC*CC];     // [mode][i*64+o]
__device__ float2 g_phi  [BB*NM];
__device__ float  g_gb   [BB*2*CC];

// ---------------- helpers ----------------
__device__ __forceinline__ float2 cmul(float2 a, float2 b) {
    return make_float2(a.x*b.x - a.y*b.y, a.x*b.y + a.y*b.x);
}
__device__ __forceinline__ float2 ffma2(float2 a, float2 b, float2 c) {
    float2 d;
    asm("fma.rn.f32x2 %0, %1, %2, %3;"
        : "=l"(reinterpret_cast<unsigned long long&>(d))
        : "l"(reinterpret_cast<unsigned long long&>(a)),
          "l"(reinterpret_cast<unsigned long long&>(b)),
          "l"(reinterpret_cast<unsigned long long&>(c)));
    return d;
}
__device__ __forceinline__ float2 fmul2(float2 a, float2 b) {
    float2 d;
    asm("mul.rn.f32x2 %0, %1, %2;"
        : "=l"(reinterpret_cast<unsigned long long&>(d))
        : "l"(reinterpret_cast<unsigned long long&>(a)),
          "l"(reinterpret_cast<unsigned long long&>(b)));
    return d;
}
// decode canonical index j -> (k_idx, m_idx)
__device__ __forceinline__ void canon_decode(int j, int& ki, int& mi) {
    if (j < 128) {
        int r = j >> 4;
        ki = (r == 0) ? 0 : 8 + r;
        mi = j & 15;
    } else {
        int t = j - 128;
        if (t < 7)      { ki = 1 + t; mi = 0; }
        else if (t == 7){ ki = 8;     mi = 0; }
        else            { ki = 8;     mi = t; }
    }
}

#define TWO_PI 6.2831853071795864f

// ---------------- K_prep: zero + wT + phi + mlp fused ----------------
__global__ void __launch_bounds__(256) k_prep(
        const float* __restrict__ wr, const float* __restrict__ wi,
        const float* __restrict__ mr, const float* __restrict__ mi,
        const float* __restrict__ emb,
        const float* __restrict__ W1, const float* __restrict__ b1,
        const float* __restrict__ W2, const float* __restrict__ b2) {
    __shared__ float sb[2112];
    int bid = blockIdx.x, tid = threadIdx.x;

    if (bid < 64) {
        float4 z = make_float4(0.f, 0.f, 0.f, 0.f);
        float4* dst = (float4*)g_xhat;
        for (int idx = bid*256 + tid; idx < BB*NCAN*CC/2; idx += 64*256)
            dst[idx] = z;
    } else if (bid < 1088) {
        int bid2 = bid - 64;
        int m0 = (bid2 & 7) * 32, n0 = (bid2 >> 3) * 32;
        int tx = tid & 31, ty = tid >> 5;
        float* tr = sb;
        float* ti = sb + 1056;
#pragma unroll
        for (int yy = 0; yy < 4; yy++) {
            int n = n0 + ty + 8*yy;
            tr[(ty+8*yy)*33 + tx] = wr[n*NM + m0 + tx];
            ti[(ty+8*yy)*33 + tx] = wi[n*NM + m0 + tx];
        }
        __syncthreads();
#pragma unroll
        for (int yy = 0; yy < 4; yy++) {
            int m = m0 + ty + 8*yy;
            g_wT[m*(CC*CC) + n0 + tx] = make_float2(tr[tx*33 + ty+8*yy],
                                                    ti[tx*33 + ty+8*yy]);
        }
    } else if (bid < 1216) {
        int bid3 = bid - 1088;
        int b = bid3 >> 5;
        int warp = tid >> 5, lane = tid & 31;
        int mode = (bid3 & 31) * 8 + warp;
        const float* e = emb + b*EMB;
        float sr = 0.f, si = 0.f;
        for (int c = lane; c < EMB; c += 32) {
            float ev = e[c];
            sr += mr[mode*EMB + c] * ev;
            si += mi[mode*EMB + c] * ev;
        }
#pragma unroll
        for (int o = 16; o; o >>= 1) {
            sr += __shfl_xor_sync(0xffffffffu, sr, o);
            si += __shfl_xor_sync(0xffffffffu, si, o);
        }
        if (lane == 0) g_phi[b*NM + mode] = make_float2(sr, si);
    } else {
        int b = bid - 1216;
        float* part = sb;
        float* hs   = sb + 256;
        int o = tid & 63, q = tid >> 6;
        const float* ep  = emb + b*EMB + q*64;
        const float* w1p = W1 + (q*64)*HID + o;
        float s = 0.f;
#pragma unroll 8
        for (int c = 0; c < 64; c++) s += ep[c] * w1p[c*HID];
        part[q*64 + o] = s;
        __syncthreads();
        if (tid < 64) {
            float v = part[tid] + part[64+tid] + part[128+tid] + part[192+tid] + b1[tid];
            hs[tid] = v / (1.f + __expf(-v));
        }
        __syncthreads();
        if (tid < 128) {
            float s2 = b2[tid];
#pragma unroll 8
            for (int h = 0; h < 64; h++) s2 += hs[h] * W2[h*(2*CC) + tid];
            g_gb[b*(2*CC) + tid] = s2;
        }
    }
}

// ---------------- K_fwd: forward NUFFT (144 canonical modes) ----------------
// grid (64 p-tiles, 3 row-groups, B). block 128 = 8 c-groups(8c) x 16 j-groups(3m).
#define GS_PAD 50
#define FWD_SMEM (64*68*4 + 64*GS_PAD*8 + 2*9*64*8)
__global__ void __launch_bounds__(128, 4) k_fwd(const float* __restrict__ x,
                                                const float* __restrict__ pos) {
    extern __shared__ char smraw[];
    float*  xs  = (float*)smraw;                        // [c][68]
    float2* gs  = (float2*)(smraw + 64*68*4);           // [p][GS_PAD]
    float2* upw = (float2*)(smraw + 64*68*4 + 64*GS_PAD*8);  // [9][64]
    float2* vpw = upw + 9*64;                                // [9][64]
    int b = blockIdx.z, kt = blockIdx.y;
    int pbase = blockIdx.x * (PP/64);
    int tid = threadIdx.x;
    int c0 = (tid >> 4) * 8;       // 8 channels per thread
    int j0 = (tid & 15) * 3;       // 3 modes per thread

    float2 acc[8][3];
#pragma unroll
    for (int i = 0; i < 8; i++)
#pragma unroll
        for (int j = 0; j < 3; j++) acc[i][j] = make_float2(0.f, 0.f);

    for (int ch = 0; ch < 4; ch++) {
        int p0 = pbase + ch*64;
        __syncthreads();
        // x chunk: 64c x 64p = 1024 float4, 8 per thread
#pragma unroll
        for (int jj = 0; jj < 8; jj++) {
            int lin = tid + 128*jj;
            int c = lin >> 4, p4 = (lin & 15) * 4;
            float4 v = *(const float4*)&x[(b*CC + c)*PP + p0 + p4];
            *(float4*)&xs[c*68 + p4] = v;
        }
        // power chains: all 128 threads, (p, u/v)
        {
            int p = tid & 63, w = tid >> 6;
            float2 ps = ((const float2*)pos)[b*PP + p0 + p];
            float ang = TWO_PI * (w ? ps.y : ps.x);
            float s, c;
            __sincosf(ang, &s, &c);
            float2 u = make_float2(c, s), t = make_float2(1.f, 0.f);
            float2* dst = w ? vpw : upw;
            dst[p] = t;
#pragma unroll
            for (int j = 1; j <= 8; j++) { t = cmul(t, u); dst[j*64 + p] = t; }
        }
        __syncthreads();
        // g build: 2 threads per p, 24 slots each (covers 48 slots)
        {
            int p = tid >> 1, part = tid & 1;
#pragma unroll
            for (int n = 0; n < 24; n++) {
                int s = part*24 + n;
                int r = 3*kt + (s >> 4), t = s & 15;
                int ki, mi;
                if (r < 8) { ki = (r == 0) ? 0 : 8 + r; mi = t; }
                else {
                    if (t < 7)       { ki = 1 + t; mi = 0; }
                    else if (t == 7) { ki = 8;     mi = 0; }
                    else             { ki = 8;     mi = t; }
                }
                int kk = ki - 8, mm = mi - 8;
                int ka = kk < 0 ? -kk : kk;
                int ma = mm < 0 ? -mm : mm;
                float2 a  = upw[ka*64 + p]; if (kk < 0) a.y  = -a.y;
                float2 bb = vpw[ma*64 + p]; if (mm < 0) bb.y = -bb.y;
                gs[p*GS_PAD + s] = cmul(a, bb);
            }
        }
        __syncthreads();
        // main: 8 channels x 3 modes per thread, p unrolled by 4 (float4 x)
        for (int p = 0; p < 64; p += 4) {
            float4 xv[8];
#pragma unroll
            for (int i = 0; i < 8; i++)
                xv[i] = *(const float4*)&xs[(c0+i)*68 + p];
#pragma unroll
            for (int pp = 0; pp < 4; pp++) {
                const float2* gp = &gs[(p+pp)*GS_PAD + j0];
                float2 g0 = gp[0], g1 = gp[1], g2 = gp[2];
#pragma unroll
                for (int i = 0; i < 8; i++) {
                    float xvv = (pp == 0) ? xv[i].x : (pp == 1) ? xv[i].y
                              : (pp == 2) ? xv[i].z : xv[i].w;
                    float2 X = make_float2(xvv, xvv);
                    acc[i][0] = ffma2(X, g0, acc[i][0]);
                    acc[i][1] = ffma2(X, g1, acc[i][1]);
                    acc[i][2] = ffma2(X, g2, acc[i][2]);
                }
            }
        }
    }
#pragma unroll
    for (int ci = 0; ci < 8; ci++)
#pragma unroll
        for (int jj = 0; jj < 3; jj++) {
            int j = kt*48 + j0 + jj;
            float* dst = (float*)&g_xhat[(b*NCAN + j)*CC + c0 + ci];
            atomicAdd(dst,     acc[ci][jj].x);
            atomicAdd(dst + 1, acc[ci][jj].y);
        }
}

// ---------------- K_mix: channel mix + modulation ----------------
__global__ void __launch_bounds__(256) k_mix() {
    __shared__ float2 xh[4][64];   // [b][i] for this mode
    int mode = blockIdx.x;
    int tid = threadIdx.x;
    int o = tid & 63, bb = tid >> 6;
    {
        int i = o, bq = bb;
        int ki = mode >> 4, mi = mode & 15;
        bool canon = (mi == 0) || (ki == 0) || (ki >= 9) || (ki == 8 && mi >= 8);
        int js; float cs;
        if (canon) {
            cs = 1.f;
            if (ki == 0)       js = mi;
            else if (ki >= 9)  js = (ki-8)*16 + mi;
            else if (ki <= 7)  js = 128 + (ki-1);
            else               js = (mi == 0) ? 135 : 128 + mi;
        } else {
            cs = -1.f;
            int ki2 = 16 - ki, mi2 = 16 - mi;
            js = (ki2 >= 9) ? (ki2-8)*16 + mi2 : 128 + mi2;
        }
        float2 v = g_xhat[(bq*NCAN + js)*CC + i];
        xh[bq][i] = make_float2(v.x, cs * v.y);
    }
    __syncthreads();
    float2 acc = make_float2(0.f, 0.f);
    const float2* wrow = g_wT + mode*(CC*CC) + o;
#pragma unroll 8
    for (int i = 0; i < CC; i++) {
        float2 w = wrow[i*CC];
        float2 xv = xh[bb][i];
        acc.x += xv.x*w.x - xv.y*w.y;
        acc.y += xv.x*w.y + xv.y*w.x;
    }
    float2 ph = g_phi[bb*NM + mode];
    g_xhat2[(bb*NM + mode)*CC + o] = cmul(ph, acc);
}

// ---------------- K_inv: inverse NUFFT (144 folded, packed-g over 2 points) --
struct InvSmem {
    float2 Ys[NCAN][10];     // folded spectral slab, 8 channels (pad 10)
    float2 apw[9][512];      // u-power chain, INTERLEAVED: [j][2*tid+pt]
    float2 wcp[CC][4];       // wc packed channel-pairs (8 channels)
    float  gam[8], bet[8], bcs[8];
};
#define INV_SMEM ((int)sizeof(InvSmem))

__global__ void __launch_bounds__(256, 2) k_inv(const float* __restrict__ x,
                                                const float* __restrict__ pos,
                                                const float* __restrict__ wc,
                                                const float* __restrict__ bc,
                                                float* __restrict__ out) {
    extern __shared__ char smraw[];
    InvSmem& S = *reinterpret_cast<InvSmem*>(smraw);
    int b = blockIdx.z, cg = blockIdx.y;
    int p0 = blockIdx.x * 512;
    int tid = threadIdx.x;
    int cbase = cg * 8;

    // folded slab: Y[j] = X2[mode_j] + conj(X2[partner])
    for (int lin = tid; lin < NCAN*8; lin += 256) {
        int j = lin >> 3, c = lin & 7;
        int ki, mi;
        canon_decode(j, ki, mi);
        float2 v = g_xhat2[(b*NM + ki*16 + mi)*CC + cbase + c];
        bool hasp = (ki >= 1) && (mi >= 1) && !(ki == 8 && mi == 8);
        if (hasp) {
            float2 q = g_xhat2[(b*NM + (16-ki)*16 + (16-mi))*CC + cbase + c];
            v.x += q.x;
            v.y -= q.y;
        }
        S.Ys[j][c] = v;
    }
    {
        int i = tid >> 2, cp = tid & 3;
        S.wcp[i][cp] = make_float2(wc[(cbase + 2*cp    )*CC + i],
                                   wc[(cbase + 2*cp + 1)*CC + i]);
    }
    if (tid < 8) {
        S.gam[tid] = g_gb[b*(2*CC) + cbase + tid];
        S.bet[tid] = g_gb[b*(2*CC) + CC + cbase + tid];
        S.bcs[tid] = bc[cbase + tid];
    }
    // chains: point0 = p0+tid, point1 = p0+256+tid.
    // bpx/bpy: v-chain re/im planes packed over the two points.
    float2 bpx[9], bpy[9];
    {
        float2 ps0 = ((const float2*)pos)[b*PP + p0 + tid];
        float2 ps1 = ((const float2*)pos)[b*PP + p0 + 256 + tid];
        float s, c;
        __sincosf(TWO_PI * ps0.x, &s, &c); float2 u0 = make_float2(c, s);
        __sincosf(TWO_PI * ps0.y, &s, &c); float2 v0 = make_float2(c, s);
        __sincosf(TWO_PI * ps1.x, &s, &c); float2 u1 = make_float2(c, s);
        __sincosf(TWO_PI * ps1.y, &s, &c); float2 v1 = make_float2(c, s);
        float2 t0 = make_float2(1.f, 0.f), t1 = make_float2(1.f, 0.f);
        *(float4*)&S.apw[0][2*tid] = make_float4(1.f, 0.f, 1.f, 0.f);
#pragma unroll
        for (int j = 1; j <= 8; j++) {
            t0 = cmul(t0, u0); t1 = cmul(t1, u1);
            *(float4*)&S.apw[j][2*tid] = make_float4(t0.x, t0.y, t1.x, t1.y);
        }
        float2 w0 = make_float2(1.f, 0.f), w1 = make_float2(1.f, 0.f);
        bpx[0] = make_float2(1.f, 1.f);
        bpy[0] = make_float2(0.f, 0.f);
#pragma unroll
        for (int j = 1; j <= 8; j++) {
            w0 = cmul(w0, v0); w1 = cmul(w1, v1);
            bpx[j] = make_float2(w0.x, w1.x);
            bpy[j] = make_float2(w0.y, w1.y);
        }
    }
    __syncthreads();

    float2 acc0[8], acc1[8];
#pragma unroll
    for (int c = 0; c < 8; c++) { acc0[c] = make_float2(0.f, 0.f); acc1[c] = make_float2(0.f, 0.f); }
    float2 accw0[4], accw1[4];
#pragma unroll
    for (int c = 0; c < 4; c++) { accw0[c] = make_float2(0.f, 0.f); accw1[c] = make_float2(0.f, 0.f); }

    // conv: direct LDG (L2-resident), 2 points
#pragma unroll 8
    for (int i = 0; i < CC; i++) {
        const float* xp = &x[(b*CC + i)*PP + p0 + tid];
        float xv0 = __ldg(xp);
        float xv1 = __ldg(xp + 256);
        float2 xa = make_float2(xv0, xv0), xb = make_float2(xv1, xv1);
#pragma unroll
        for (int cp = 0; cp < 4; cp++) {
            float2 w = S.wcp[i][cp];
            accw0[cp] = ffma2(xa, w, accw0[cp]);
            accw1[cp] = ffma2(xb, w, accw1[cp]);
        }
    }

#define INV_BODY(JIDX)                                                         \
    {                                                                          \
        const float4* xp = (const float4*)&S.Ys[(JIDX)][0];                    \
        _Pragma("unroll")                                                      \
        for (int q = 0; q < 4; q++) {                                          \
            float4 xq = xp[q];                                                 \
            float2 ya = make_float2(xq.x, xq.y);                               \
            float2 yb = make_float2(xq.z, xq.w);                               \
            acc0[2*q]   = ffma2(ya, g0, acc0[2*q]);                            \
            acc0[2*q+1] = ffma2(yb, g0, acc0[2*q+1]);                          \
            acc1[2*q]   = ffma2(ya, g1, acc1[2*q]);                            \
            acc1[2*q+1] = ffma2(yb, g1, acc1[2*q+1]);                          \
        }                                                                      \
    }

    // rows 0..7: packed g-construction over the two points.
    // a: ay = sk*av.y (sk=-1 for r==0). b: by = st*bpy (st=-1 for t<8).
    // byN = -st*bpy  =>  gx = ax*bx + ay*byN ; gy = ay*bx - ax*byN.
    for (int r = 0; r < 8; r++) {
        int ja = (r == 0) ? 8 : r;
        float4 qv = *(const float4*)&S.apw[ja][2*tid];
        float2 axp = make_float2(qv.x, qv.z);
        float2 ayp = make_float2(qv.y, qv.w);
        if (r == 0) { ayp.x = -ayp.x; ayp.y = -ayp.y; }
        float2 naxp = make_float2(-axp.x, -axp.y);
#pragma unroll
        for (int t = 0; t < 16; t++) {
            float2 bvx = (t < 8) ? bpx[8-t] : bpx[t-8];
            float2 byN = (t < 8) ? bpy[8-t]
                                 : make_float2(-bpy[t-8].x, -bpy[t-8].y);
            float2 gxp = ffma2(ayp,  byN, fmul2(axp, bvx));
            float2 gyp = ffma2(naxp, byN, fmul2(ayp, bvx));
            float2 g0 = make_float2(gxp.x, gyp.x);
            float2 g1 = make_float2(gxp.y, gyp.y);
            INV_BODY(r*16 + t)
        }
    }
    // row 8 (oddballs)
#pragma unroll
    for (int t = 0; t < 16; t++) {
        float2 g0, g1;
        if (t < 7) {
            // a = conj(u^{7-t}), b = conj(v^8):  ay = -av.y, st=-1 -> byN = +bpy[8]
            float4 qv = *(const float4*)&S.apw[7-t][2*tid];
            float2 axp = make_float2(qv.x, qv.z);
            float2 ayp = make_float2(-qv.y, -qv.w);
            float2 naxp = make_float2(-axp.x, -axp.y);
            float2 bvx = bpx[8], byN = bpy[8];
            float2 gxp = ffma2(ayp,  byN, fmul2(axp, bvx));
            float2 gyp = ffma2(naxp, byN, fmul2(ayp, bvx));
            g0 = make_float2(gxp.x, gyp.x);
            g1 = make_float2(gxp.y, gyp.y);
        } else if (t == 7) {
            // a = 1, b = conj(v^8)
            g0 = make_float2(bpx[8].x, -bpy[8].x);
            g1 = make_float2(bpx[8].y, -bpy[8].y);
        } else {
            // a = 1, b = v^{t-8}
            g0 = make_float2(bpx[t-8].x, bpy[t-8].x);
            g1 = make_float2(bpx[t-8].y, bpy[t-8].y);
        }
        INV_BODY(128 + t)
    }
#undef INV_BODY

    float inv = 2.0f / (float)PP;
#pragma unroll
    for (int c = 0; c < 8; c++) {
        float cwa = (c & 1) ? accw0[c >> 1].y : accw0[c >> 1].x;
        float cwb = (c & 1) ? accw1[c >> 1].y : accw1[c >> 1].x;
        float gmc = 1.f + S.gam[c], btc = S.bet[c], bcc = S.bcs[c];
        float x1a = (acc0[c].x + acc0[c].y) * inv;
        float x2a = (cwa + bcc) * gmc + btc;
        float sa = x1a + x2a;
        float x1b = (acc1[c].x + acc1[c].y) * inv;
        float x2b = (cwb + bcc) * gmc + btc;
        float sb = x1b + x2b;
        float* op = &out[(b*CC + cbase + c)*PP + p0 + tid];
        op[0]   = sa / (1.f + __expf(-sa));
        op[256] = sb / (1.f + __expf(-sb));
    }
}

// ---------------- launcher ----------------
extern "C" void kernel_launch(void* const* d_in, const int* in_sizes, int n_in,
                              void* d_out, int out_size) {
    (void)in_sizes; (void)n_in; (void)out_size;
    const float* x        = (const float*)d_in[0];
    const float* pos      = (const float*)d_in[1];
    const float* emb      = (const float*)d_in[2];
    const float* w_real   = (const float*)d_in[3];
    const float* w_imag   = (const float*)d_in[4];
    const float* mod_real = (const float*)d_in[5];
    const float* mod_imag = (const float*)d_in[6];
    const float* W1       = (const float*)d_in[7];
    const float* b1       = (const float*)d_in[8];
    const float* W2       = (const float*)d_in[9];
    const float* b2       = (const float*)d_in[10];
    const float* wc       = (const float*)d_in[11];
    const float* bc       = (const float*)d_in[12];
    float* out = (float*)d_out;

    cudaFuncSetAttribute(k_fwd, cudaFuncAttributeMaxDynamicSharedMemorySize, FWD_SMEM);
    cudaFuncSetAttribute(k_inv, cudaFuncAttributeMaxDynamicSharedMemorySize, INV_SMEM);

    k_prep<<<1220, 256>>>(w_real, w_imag, mod_real, mod_imag, emb, W1, b1, W2, b2);
    k_fwd<<<dim3(64, 3, BB), 128, FWD_SMEM>>>(x, pos);
    k_mix<<<NM, 256>>>();
    k_inv<<<dim3(PP/512, CC/8, BB), 256, INV_SMEM>>>(x, pos, wc, bc, out);
}

// round 15
// speedup vs baseline: 1.2303x; 1.2303x over previous
#include <cuda_runtime.h>
#include <cuda_bf16.h>

// ---------------- problem constants ----------------
#define BB 4
#define CC 64
#define PP 16384
#define NM 256      // 16x16 modes, mode = k_idx*16 + m_idx, k = k_idx-8, m = m_idx-8
#define NCAN 144    // canonical modes (Hermitian-reduced)
#define EMB 256
#define HID 64

// Canonical layout: j = r*16 + t, r in 0..8
//  r=0        : (k_idx=0,    m_idx=t)
//  r=1..7     : (k_idx=8+r,  m_idx=t)
//  r=8, t<7   : (k_idx=1+t,  m_idx=0)
//  r=8, t==7  : (k_idx=8,    m_idx=0)
//  r=8, t>=8  : (k_idx=8,    m_idx=t)

// ---------------- device scratch ----------------
__device__ float2 g_xhat [BB*NM*CC];     // only first BB*NCAN*CC used, [b][j][c]
__device__ float2 g_xhat2[BB*NM*CC];     // full 256 modes, [b][mode][c]
__device__ float2 g_wT   [NM*CC*CC];     // [mode][i*64+o]
__device__ float2 g_phi  [BB*NM];
__device__ float  g_gb   [BB*2*CC];

// ---------------- helpers ----------------
__device__ __forceinline__ float2 cmul(float2 a, float2 b) {
    return make_float2(a.x*b.x - a.y*b.y, a.x*b.y + a.y*b.x);
}
__device__ __forceinline__ float2 ffma2(float2 a, float2 b, float2 c) {
    float2 d;
    asm("fma.rn.f32x2 %0, %1, %2, %3;"
        : "=l"(reinterpret_cast<unsigned long long&>(d))
        : "l"(reinterpret_cast<unsigned long long&>(a)),
          "l"(reinterpret_cast<unsigned long long&>(b)),
          "l"(reinterpret_cast<unsigned long long&>(c)));
    return d;
}
// vector atomic add of a complex value (halves REDG lane-ops vs 2 scalars)
__device__ __forceinline__ void red_add_f32x2(float2* addr, float2 v) {
    asm volatile("red.global.add.v2.f32 [%0], {%1, %2};"
                 :: "l"(addr), "f"(v.x), "f"(v.y) : "memory");
}
// decode canonical index j -> (k_idx, m_idx)
__device__ __forceinline__ void canon_decode(int j, int& ki, int& mi) {
    if (j < 128) {
        int r = j >> 4;
        ki = (r == 0) ? 0 : 8 + r;
        mi = j & 15;
    } else {
        int t = j - 128;
        if (t < 7)      { ki = 1 + t; mi = 0; }
        else if (t == 7){ ki = 8;     mi = 0; }
        else            { ki = 8;     mi = t; }
    }
}

#define TWO_PI 6.2831853071795864f

// ---------------- K_prep: zero + wT + phi + mlp fused ----------------
__global__ void __launch_bounds__(256) k_prep(
        const float* __restrict__ wr, const float* __restrict__ wi,
        const float* __restrict__ mr, const float* __restrict__ mi,
        const float* __restrict__ emb,
        const float* __restrict__ W1, const float* __restrict__ b1,
        const float* __restrict__ W2, const float* __restrict__ b2) {
    __shared__ float sb[2112];
    int bid = blockIdx.x, tid = threadIdx.x;

    if (bid < 64) {
        float4 z = make_float4(0.f, 0.f, 0.f, 0.f);
        float4* dst = (float4*)g_xhat;
        for (int idx = bid*256 + tid; idx < BB*NCAN*CC/2; idx += 64*256)
            dst[idx] = z;
    } else if (bid < 1088) {
        int bid2 = bid - 64;
        int m0 = (bid2 & 7) * 32, n0 = (bid2 >> 3) * 32;
        int tx = tid & 31, ty = tid >> 5;
        float* tr = sb;
        float* ti = sb + 1056;
#pragma unroll
        for (int yy = 0; yy < 4; yy++) {
            int n = n0 + ty + 8*yy;
            tr[(ty+8*yy)*33 + tx] = wr[n*NM + m0 + tx];
            ti[(ty+8*yy)*33 + tx] = wi[n*NM + m0 + tx];
        }
        __syncthreads();
#pragma unroll
        for (int yy = 0; yy < 4; yy++) {
            int m = m0 + ty + 8*yy;
            g_wT[m*(CC*CC) + n0 + tx] = make_float2(tr[tx*33 + ty+8*yy],
                                                    ti[tx*33 + ty+8*yy]);
        }
    } else if (bid < 1216) {
        int bid3 = bid - 1088;
        int b = bid3 >> 5;
        int warp = tid >> 5, lane = tid & 31;
        int mode = (bid3 & 31) * 8 + warp;
        const float* e = emb + b*EMB;
        float sr = 0.f, si = 0.f;
        for (int c = lane; c < EMB; c += 32) {
            float ev = e[c];
            sr += mr[mode*EMB + c] * ev;
            si += mi[mode*EMB + c] * ev;
        }
#pragma unroll
        for (int o = 16; o; o >>= 1) {
            sr += __shfl_xor_sync(0xffffffffu, sr, o);
            si += __shfl_xor_sync(0xffffffffu, si, o);
        }
        if (lane == 0) g_phi[b*NM + mode] = make_float2(sr, si);
    } else {
        int b = bid - 1216;
        float* part = sb;
        float* hs   = sb + 256;
        int o = tid & 63, q = tid >> 6;
        const float* ep  = emb + b*EMB + q*64;
        const float* w1p = W1 + (q*64)*HID + o;
        float s = 0.f;
#pragma unroll 8
        for (int c = 0; c < 64; c++) s += ep[c] * w1p[c*HID];
        part[q*64 + o] = s;
        __syncthreads();
        if (tid < 64) {
            float v = part[tid] + part[64+tid] + part[128+tid] + part[192+tid] + b1[tid];
            hs[tid] = v / (1.f + __expf(-v));
        }
        __syncthreads();
        if (tid < 128) {
            float s2 = b2[tid];
#pragma unroll 8
            for (int h = 0; h < 64; h++) s2 += hs[h] * W2[h*(2*CC) + tid];
            g_gb[b*(2*CC) + tid] = s2;
        }
    }
}

// ---------------- K_fwd: forward NUFFT (144 canonical modes) ----------------
// grid (64 p-tiles, 3 row-groups, B). block 128 = 8 c-groups(8c) x 16 j-groups(3m).
#define GS_PAD 50
#define FWD_SMEM (64*68*4 + 64*GS_PAD*8 + 2*9*64*8)
__global__ void __launch_bounds__(128, 4) k_fwd(const float* __restrict__ x,
                                                const float* __restrict__ pos) {
    extern __shared__ char smraw[];
    float*  xs  = (float*)smraw;                        // [c][68]
    float2* gs  = (float2*)(smraw + 64*68*4);           // [p][GS_PAD]
    float2* upw = (float2*)(smraw + 64*68*4 + 64*GS_PAD*8);  // [9][64]
    float2* vpw = upw + 9*64;                                // [9][64]
    int b = blockIdx.z, kt = blockIdx.y;
    int pbase = blockIdx.x * (PP/64);
    int tid = threadIdx.x;
    int c0 = (tid >> 4) * 8;       // 8 channels per thread
    int j0 = (tid & 15) * 3;       // 3 modes per thread

    float2 acc[8][3];
#pragma unroll
    for (int i = 0; i < 8; i++)
#pragma unroll
        for (int j = 0; j < 3; j++) acc[i][j] = make_float2(0.f, 0.f);

    for (int ch = 0; ch < 4; ch++) {
        int p0 = pbase + ch*64;
        __syncthreads();
        // x chunk: 64c x 64p = 1024 float4, 8 per thread
#pragma unroll
        for (int jj = 0; jj < 8; jj++) {
            int lin = tid + 128*jj;
            int c = lin >> 4, p4 = (lin & 15) * 4;
            float4 v = *(const float4*)&x[(b*CC + c)*PP + p0 + p4];
            *(float4*)&xs[c*68 + p4] = v;
        }
        // power chains: all 128 threads, (p, u/v)
        {
            int p = tid & 63, w = tid >> 6;
            float2 ps = ((const float2*)pos)[b*PP + p0 + p];
            float ang = TWO_PI * (w ? ps.y : ps.x);
            float s, c;
            __sincosf(ang, &s, &c);
            float2 u = make_float2(c, s), t = make_float2(1.f, 0.f);
            float2* dst = w ? vpw : upw;
            dst[p] = t;
#pragma unroll
            for (int j = 1; j <= 8; j++) { t = cmul(t, u); dst[j*64 + p] = t; }
        }
        __syncthreads();
        // g build: 2 threads per p, 24 slots each (covers 48 slots)
        {
            int p = tid >> 1, part = tid & 1;
#pragma unroll
            for (int n = 0; n < 24; n++) {
                int s = part*24 + n;
                int r = 3*kt + (s >> 4), t = s & 15;
                int ki, mi;
                if (r < 8) { ki = (r == 0) ? 0 : 8 + r; mi = t; }
                else {
                    if (t < 7)       { ki = 1 + t; mi = 0; }
                    else if (t == 7) { ki = 8;     mi = 0; }
                    else             { ki = 8;     mi = t; }
                }
                int kk = ki - 8, mm = mi - 8;
                int ka = kk < 0 ? -kk : kk;
                int ma = mm < 0 ? -mm : mm;
                float2 a  = upw[ka*64 + p]; if (kk < 0) a.y  = -a.y;
                float2 bb = vpw[ma*64 + p]; if (mm < 0) bb.y = -bb.y;
                gs[p*GS_PAD + s] = cmul(a, bb);
            }
        }
        __syncthreads();
        // main: 8 channels x 3 modes per thread, p unrolled by 4 (float4 x)
        for (int p = 0; p < 64; p += 4) {
            float4 xv[8];
#pragma unroll
            for (int i = 0; i < 8; i++)
                xv[i] = *(const float4*)&xs[(c0+i)*68 + p];
#pragma unroll
            for (int pp = 0; pp < 4; pp++) {
                const float2* gp = &gs[(p+pp)*GS_PAD + j0];
                float2 g0 = gp[0], g1 = gp[1], g2 = gp[2];
#pragma unroll
                for (int i = 0; i < 8; i++) {
                    float xvv = (pp == 0) ? xv[i].x : (pp == 1) ? xv[i].y
                              : (pp == 2) ? xv[i].z : xv[i].w;
                    float2 X = make_float2(xvv, xvv);
                    acc[i][0] = ffma2(X, g0, acc[i][0]);
                    acc[i][1] = ffma2(X, g1, acc[i][1]);
                    acc[i][2] = ffma2(X, g2, acc[i][2]);
                }
            }
        }
    }
#pragma unroll
    for (int ci = 0; ci < 8; ci++)
#pragma unroll
        for (int jj = 0; jj < 3; jj++) {
            int j = kt*48 + j0 + jj;
            red_add_f32x2(&g_xhat[(b*NCAN + j)*CC + c0 + ci], acc[ci][jj]);
        }
}

// ---------------- K_mix: channel mix + modulation ----------------
__global__ void __launch_bounds__(256) k_mix() {
    __shared__ float2 xh[4][64];   // [b][i] for this mode
    int mode = blockIdx.x;
    int tid = threadIdx.x;
    int o = tid & 63, bb = tid >> 6;
    {
        int i = o, bq = bb;
        int ki = mode >> 4, mi = mode & 15;
        bool canon = (mi == 0) || (ki == 0) || (ki >= 9) || (ki == 8 && mi >= 8);
        int js; float cs;
        if (canon) {
            cs = 1.f;
            if (ki == 0)       js = mi;
            else if (ki >= 9)  js = (ki-8)*16 + mi;
            else if (ki <= 7)  js = 128 + (ki-1);
            else               js = (mi == 0) ? 135 : 128 + mi;
        } else {
            cs = -1.f;
            int ki2 = 16 - ki, mi2 = 16 - mi;
            js = (ki2 >= 9) ? (ki2-8)*16 + mi2 : 128 + mi2;
        }
        float2 v = g_xhat[(bq*NCAN + js)*CC + i];
        xh[bq][i] = make_float2(v.x, cs * v.y);
    }
    __syncthreads();
    float2 acc = make_float2(0.f, 0.f);
    const float2* wrow = g_wT + mode*(CC*CC) + o;
#pragma unroll 8
    for (int i = 0; i < CC; i++) {
        float2 w = wrow[i*CC];
        float2 xv = xh[bb][i];
        acc.x += xv.x*w.x - xv.y*w.y;
        acc.y += xv.x*w.y + xv.y*w.x;
    }
    float2 ph = g_phi[bb*NM + mode];
    g_xhat2[(bb*NM + mode)*CC + o] = cmul(ph, acc);
}

// ---------------- K_inv: inverse NUFFT (144 folded, 2 points x 8 ch/thread) --
struct InvSmem {
    float2 Ys[NCAN][10];     // folded spectral slab, 8 channels (pad 10)
    float2 apw[9][512];      // u-power chain for 512 points
    float2 wcp[CC][4];       // wc packed channel-pairs (8 channels)
    float  gam[8], bet[8], bcs[8];
};
#define INV_SMEM ((int)sizeof(InvSmem))

__global__ void __launch_bounds__(256, 2) k_inv(const float* __restrict__ x,
                                                const float* __restrict__ pos,
                                                const float* __restrict__ wc,
                                                const float* __restrict__ bc,
                                                float* __restrict__ out) {
    extern __shared__ char smraw[];
    InvSmem& S = *reinterpret_cast<InvSmem*>(smraw);
    int b = blockIdx.z, cg = blockIdx.y;
    int p0 = blockIdx.x * 512;
    int tid = threadIdx.x;
    int cbase = cg * 8;

    // folded slab: Y[j] = X2[mode_j] + conj(X2[partner])
    for (int lin = tid; lin < NCAN*8; lin += 256) {
        int j = lin >> 3, c = lin & 7;
        int ki, mi;
        canon_decode(j, ki, mi);
        float2 v = g_xhat2[(b*NM + ki*16 + mi)*CC + cbase + c];
        bool hasp = (ki >= 1) && (mi >= 1) && !(ki == 8 && mi == 8);
        if (hasp) {
            float2 q = g_xhat2[(b*NM + (16-ki)*16 + (16-mi))*CC + cbase + c];
            v.x += q.x;
            v.y -= q.y;
        }
        S.Ys[j][c] = v;
    }
    {
        int i = tid >> 2, cp = tid & 3;
        S.wcp[i][cp] = make_float2(wc[(cbase + 2*cp    )*CC + i],
                                   wc[(cbase + 2*cp + 1)*CC + i]);
    }
    if (tid < 8) {
        S.gam[tid] = g_gb[b*(2*CC) + cbase + tid];
        S.bet[tid] = g_gb[b*(2*CC) + CC + cbase + tid];
        S.bcs[tid] = bc[cbase + tid];
    }
    float2 bp0[9], bp1[9];
    {
        float2 ps = ((const float2*)pos)[b*PP + p0 + tid];
        float s, c;
        __sincosf(TWO_PI * ps.x, &s, &c); float2 u = make_float2(c, s);
        __sincosf(TWO_PI * ps.y, &s, &c); float2 v = make_float2(c, s);
        float2 t = make_float2(1.f, 0.f);
        S.apw[0][tid] = t;
#pragma unroll
        for (int j = 1; j <= 8; j++) { t = cmul(t, u); S.apw[j][tid] = t; }
        bp0[0] = make_float2(1.f, 0.f);
        t = make_float2(1.f, 0.f);
#pragma unroll
        for (int j = 1; j <= 8; j++) { t = cmul(t, v); bp0[j] = t; }

        ps = ((const float2*)pos)[b*PP + p0 + 256 + tid];
        __sincosf(TWO_PI * ps.x, &s, &c); u = make_float2(c, s);
        __sincosf(TWO_PI * ps.y, &s, &c); v = make_float2(c, s);
        t = make_float2(1.f, 0.f);
        S.apw[0][256 + tid] = t;
#pragma unroll
        for (int j = 1; j <= 8; j++) { t = cmul(t, u); S.apw[j][256 + tid] = t; }
        bp1[0] = make_float2(1.f, 0.f);
        t = make_float2(1.f, 0.f);
#pragma unroll
        for (int j = 1; j <= 8; j++) { t = cmul(t, v); bp1[j] = t; }
    }
    __syncthreads();

    float2 acc0[8], acc1[8];
#pragma unroll
    for (int c = 0; c < 8; c++) { acc0[c] = make_float2(0.f, 0.f); acc1[c] = make_float2(0.f, 0.f); }
    float2 accw0[4], accw1[4];
#pragma unroll
    for (int c = 0; c < 4; c++) { accw0[c] = make_float2(0.f, 0.f); accw1[c] = make_float2(0.f, 0.f); }

    // conv: direct LDG (L2-resident), 2 points
#pragma unroll 8
    for (int i = 0; i < CC; i++) {
        const float* xp = &x[(b*CC + i)*PP + p0 + tid];
        float xv0 = __ldg(xp);
        float xv1 = __ldg(xp + 256);
        float2 xa = make_float2(xv0, xv0), xb = make_float2(xv1, xv1);
#pragma unroll
        for (int cp = 0; cp < 4; cp++) {
            float2 w = S.wcp[i][cp];
            accw0[cp] = ffma2(xa, w, accw0[cp]);
            accw1[cp] = ffma2(xb, w, accw1[cp]);
        }
    }

#define INV_BODY(JIDX)                                                         \
    {                                                                          \
        const float4* xp = (const float4*)&S.Ys[(JIDX)][0];                    \
        _Pragma("unroll")                                                      \
        for (int q = 0; q < 4; q++) {                                          \
            float4 xq = xp[q];                                                 \
            float2 ya = make_float2(xq.x, xq.y);                               \
            float2 yb = make_float2(xq.z, xq.w);                               \
            acc0[2*q]   = ffma2(ya, g0, acc0[2*q]);                            \
            acc0[2*q+1] = ffma2(yb, g0, acc0[2*q+1]);                          \
            acc1[2*q]   = ffma2(ya, g1, acc1[2*q]);                            \
            acc1[2*q+1] = ffma2(yb, g1, acc1[2*q+1]);                          \
        }                                                                      \
    }

    // rows 0..7
    for (int r = 0; r < 8; r++) {
        int ja = (r == 0) ? 8 : r;
        float sk = (r == 0) ? -1.f : 1.f;
        float2 av0 = S.apw[ja][tid];
        float2 av1 = S.apw[ja][256 + tid];
        float ax0 = av0.x, ay0 = sk * av0.y;
        float ax1 = av1.x, ay1 = sk * av1.y;
#pragma unroll
        for (int t = 0; t < 16; t++) {
            float2 bv0 = (t < 8) ? make_float2(bp0[8-t].x, -bp0[8-t].y) : bp0[t-8];
            float2 bv1 = (t < 8) ? make_float2(bp1[8-t].x, -bp1[8-t].y) : bp1[t-8];
            float2 g0 = make_float2(ax0*bv0.x - ay0*bv0.y, ax0*bv0.y + ay0*bv0.x);
            float2 g1 = make_float2(ax1*bv1.x - ay1*bv1.y, ax1*bv1.y + ay1*bv1.x);
            INV_BODY(r*16 + t)
        }
    }
    // row 8 (oddballs)
#pragma unroll
    for (int t = 0; t < 16; t++) {
        float2 g0, g1;
        if (t < 7) {
            float2 av0 = S.apw[7-t][tid];
            float2 av1 = S.apw[7-t][256 + tid];
            float ax0 = av0.x, ay0 = -av0.y;
            float ax1 = av1.x, ay1 = -av1.y;
            float2 bv0 = make_float2(bp0[8].x, -bp0[8].y);
            float2 bv1 = make_float2(bp1[8].x, -bp1[8].y);
            g0 = make_float2(ax0*bv0.x - ay0*bv0.y, ax0*bv0.y + ay0*bv0.x);
            g1 = make_float2(ax1*bv1.x - ay1*bv1.y, ax1*bv1.y + ay1*bv1.x);
        } else if (t == 7) {
            g0 = make_float2(bp0[8].x, -bp0[8].y);
            g1 = make_float2(bp1[8].x, -bp1[8].y);
        } else {
            g0 = bp0[t-8];
            g1 = bp1[t-8];
        }
        INV_BODY(128 + t)
    }
#undef INV_BODY

    float inv = 2.0f / (float)PP;
#pragma unroll
    for (int c = 0; c < 8; c++) {
        float cwa = (c & 1) ? accw0[c >> 1].y : accw0[c >> 1].x;
        float cwb = (c & 1) ? accw1[c >> 1].y : accw1[c >> 1].x;
        float gmc = 1.f + S.gam[c], btc = S.bet[c], bcc = S.bcs[c];
        float x1a = (acc0[c].x + acc0[c].y) * inv;
        float x2a = (cwa + bcc) * gmc + btc;
        float sa = x1a + x2a;
        float x1b = (acc1[c].x + acc1[c].y) * inv;
        float x2b = (cwb + bcc) * gmc + btc;
        float sb = x1b + x2b;
        float* op = &out[(b*CC + cbase + c)*PP + p0 + tid];
        op[0]   = sa / (1.f + __expf(-sa));
        op[256] = sb / (1.f + __expf(-sb));
    }
}

// ---------------- launcher ----------------
extern "C" void kernel_launch(void* const* d_in, const int* in_sizes, int n_in,
                              void* d_out, int out_size) {
    (void)in_sizes; (void)n_in; (void)out_size;
    const float* x        = (const float*)d_in[0];
    const float* pos      = (const float*)d_in[1];
    const float* emb      = (const float*)d_in[2];
    const float* w_real   = (const float*)d_in[3];
    const float* w_imag   = (const float*)d_in[4];
    const float* mod_real = (const float*)d_in[5];
    const float* mod_imag = (const float*)d_in[6];
    const float* W1       = (const float*)d_in[7];
    const float* b1       = (const float*)d_in[8];
    const float* W2       = (const float*)d_in[9];
    const float* b2       = (const float*)d_in[10];
    const float* wc       = (const float*)d_in[11];
    const float* bc       = (const float*)d_in[12];
    float* out = (float*)d_out;

    cudaFuncSetAttribute(k_fwd, cudaFuncAttributeMaxDynamicSharedMemorySize, FWD_SMEM);
    cudaFuncSetAttribute(k_inv, cudaFuncAttributeMaxDynamicSharedMemorySize, INV_SMEM);

    k_prep<<<1220, 256>>>(w_real, w_imag, mod_real, mod_imag, emb, W1, b1, W2, b2);
    k_fwd<<<dim3(64, 3, BB), 128, FWD_SMEM>>>(x, pos);
    k_mix<<<NM, 256>>>();
    k_inv<<<dim3(PP/512, CC/8, BB), 256, INV_SMEM>>>(x, pos, wc, bc, out);
}

// round 17
// speedup vs baseline: 1.2475x; 1.0140x over previous
#include <cuda_runtime.h>
#include <cuda_bf16.h>

// ---------------- problem constants ----------------
#define BB 4
#define CC 64
#define PP 16384
#define NM 256      // 16x16 modes, mode = k_idx*16 + m_idx, k = k_idx-8, m = m_idx-8
#define NCAN 144    // canonical modes (Hermitian-reduced)
#define EMB 256
#define HID 64

// Canonical layout: j = r*16 + t, r in 0..8
//  r=0        : (k_idx=0,    m_idx=t)
//  r=1..7     : (k_idx=8+r,  m_idx=t)
//  r=8, t<7   : (k_idx=1+t,  m_idx=0)
//  r=8, t==7  : (k_idx=8,    m_idx=0)
//  r=8, t>=8  : (k_idx=8,    m_idx=t)

// ---------------- device scratch ----------------
__device__ float2 g_xhat [BB*NM*CC];     // only first BB*NCAN*CC used, [b][j][c]
__device__ float2 g_xhat2[BB*NM*CC];     // full 256 modes, [b][mode][c] (atomically accumulated)
__device__ float4 g_wT4  [NM*CC*CC];     // [mode][i*64+o] = (wx, wy, -wy, wx)
__device__ float2 g_phi  [BB*NM];
__device__ float  g_gb   [BB*2*CC];

// ---------------- helpers ----------------
__device__ __forceinline__ float2 cmul(float2 a, float2 b) {
    return make_float2(a.x*b.x - a.y*b.y, a.x*b.y + a.y*b.x);
}
__device__ __forceinline__ float2 ffma2(float2 a, float2 b, float2 c) {
    float2 d;
    asm("fma.rn.f32x2 %0, %1, %2, %3;"
        : "=l"(reinterpret_cast<unsigned long long&>(d))
        : "l"(reinterpret_cast<unsigned long long&>(a)),
          "l"(reinterpret_cast<unsigned long long&>(b)),
          "l"(reinterpret_cast<unsigned long long&>(c)));
    return d;
}
// vector atomic add of a complex value (halves REDG lane-ops vs 2 scalars)
__device__ __forceinline__ void red_add_f32x2(float2* addr, float2 v) {
    asm volatile("red.global.add.v2.f32 [%0], {%1, %2};"
                 :: "l"(addr), "f"(v.x), "f"(v.y) : "memory");
}
// decode canonical index j -> (k_idx, m_idx)
__device__ __forceinline__ void canon_decode(int j, int& ki, int& mi) {
    if (j < 128) {
        int r = j >> 4;
        ki = (r == 0) ? 0 : 8 + r;
        mi = j & 15;
    } else {
        int t = j - 128;
        if (t < 7)      { ki = 1 + t; mi = 0; }
        else if (t == 7){ ki = 8;     mi = 0; }
        else            { ki = 8;     mi = t; }
    }
}

#define TWO_PI 6.2831853071795864f

// ---------------- K_prep: zero + wT4 + phi + mlp fused ----------------
__global__ void __launch_bounds__(256) k_prep(
        const float* __restrict__ wr, const float* __restrict__ wi,
        const float* __restrict__ mr, const float* __restrict__ mi,
        const float* __restrict__ emb,
        const float* __restrict__ W1, const float* __restrict__ b1,
        const float* __restrict__ W2, const float* __restrict__ b2) {
    __shared__ float sb[2112];
    int bid = blockIdx.x, tid = threadIdx.x;

    if (bid < 64) {
        float4 z = make_float4(0.f, 0.f, 0.f, 0.f);
        float4* d1 = (float4*)g_xhat;
        for (int idx = bid*256 + tid; idx < BB*NCAN*CC/2; idx += 64*256)
            d1[idx] = z;
        float4* d2 = (float4*)g_xhat2;
        for (int idx = bid*256 + tid; idx < BB*NM*CC/2; idx += 64*256)
            d2[idx] = z;
    } else if (bid < 1088) {
        int bid2 = bid - 64;
        int m0 = (bid2 & 7) * 32, n0 = (bid2 >> 3) * 32;
        int tx = tid & 31, ty = tid >> 5;
        float* tr = sb;
        float* ti = sb + 1056;
#pragma unroll
        for (int yy = 0; yy < 4; yy++) {
            int n = n0 + ty + 8*yy;
            tr[(ty+8*yy)*33 + tx] = wr[n*NM + m0 + tx];
            ti[(ty+8*yy)*33 + tx] = wi[n*NM + m0 + tx];
        }
        __syncthreads();
#pragma unroll
        for (int yy = 0; yy < 4; yy++) {
            int m = m0 + ty + 8*yy;
            float wrv = tr[tx*33 + ty+8*yy];
            float wiv = ti[tx*33 + ty+8*yy];
            g_wT4[m*(CC*CC) + n0 + tx] = make_float4(wrv, wiv, -wiv, wrv);
        }
    } else if (bid < 1216) {
        int bid3 = bid - 1088;
        int b = bid3 >> 5;
        int warp = tid >> 5, lane = tid & 31;
        int mode = (bid3 & 31) * 8 + warp;
        const float* e = emb + b*EMB;
        float sr = 0.f, si = 0.f;
        for (int c = lane; c < EMB; c += 32) {
            float ev = e[c];
            sr += mr[mode*EMB + c] * ev;
            si += mi[mode*EMB + c] * ev;
        }
#pragma unroll
        for (int o = 16; o; o >>= 1) {
            sr += __shfl_xor_sync(0xffffffffu, sr, o);
            si += __shfl_xor_sync(0xffffffffu, si, o);
        }
        if (lane == 0) g_phi[b*NM + mode] = make_float2(sr, si);
    } else {
        int b = bid - 1216;
        float* part = sb;
        float* hs   = sb + 256;
        int o = tid & 63, q = tid >> 6;
        const float* ep  = emb + b*EMB + q*64;
        const float* w1p = W1 + (q*64)*HID + o;
        float s = 0.f;
#pragma unroll 8
        for (int c = 0; c < 64; c++) s += ep[c] * w1p[c*HID];
        part[q*64 + o] = s;
        __syncthreads();
        if (tid < 64) {
            float v = part[tid] + part[64+tid] + part[128+tid] + part[192+tid] + b1[tid];
            hs[tid] = v / (1.f + __expf(-v));
        }
        __syncthreads();
        if (tid < 128) {
            float s2 = b2[tid];
#pragma unroll 8
            for (int h = 0; h < 64; h++) s2 += hs[h] * W2[h*(2*CC) + tid];
            g_gb[b*(2*CC) + tid] = s2;
        }
    }
}

// ---------------- K_fwd: forward NUFFT (144 canonical modes) ----------------
// grid (64 p-tiles, 3 row-groups, B). block 128 = 8 c-groups(8c) x 16 j-groups(3m).
#define GS_PAD 50
#define FWD_SMEM (64*68*4 + 64*GS_PAD*8 + 2*9*64*8)
__global__ void __launch_bounds__(128, 4) k_fwd(const float* __restrict__ x,
                                                const float* __restrict__ pos) {
    extern __shared__ char smraw[];
    float*  xs  = (float*)smraw;                        // [c][68]
    float2* gs  = (float2*)(smraw + 64*68*4);           // [p][GS_PAD]
    float2* upw = (float2*)(smraw + 64*68*4 + 64*GS_PAD*8);  // [9][64]
    float2* vpw = upw + 9*64;                                // [9][64]
    int b = blockIdx.z, kt = blockIdx.y;
    int pbase = blockIdx.x * (PP/64);
    int tid = threadIdx.x;
    int c0 = (tid >> 4) * 8;       // 8 channels per thread
    int j0 = (tid & 15) * 3;       // 3 modes per thread

    float2 acc[8][3];
#pragma unroll
    for (int i = 0; i < 8; i++)
#pragma unroll
        for (int j = 0; j < 3; j++) acc[i][j] = make_float2(0.f, 0.f);

    for (int ch = 0; ch < 4; ch++) {
        int p0 = pbase + ch*64;
        __syncthreads();
        // x chunk: 64c x 64p = 1024 float4, 8 per thread
#pragma unroll
        for (int jj = 0; jj < 8; jj++) {
            int lin = tid + 128*jj;
            int c = lin >> 4, p4 = (lin & 15) * 4;
            float4 v = *(const float4*)&x[(b*CC + c)*PP + p0 + p4];
            *(float4*)&xs[c*68 + p4] = v;
        }
        // power chains: all 128 threads, (p, u/v)
        {
            int p = tid & 63, w = tid >> 6;
            float2 ps = ((const float2*)pos)[b*PP + p0 + p];
            float ang = TWO_PI * (w ? ps.y : ps.x);
            float s, c;
            __sincosf(ang, &s, &c);
            float2 u = make_float2(c, s), t = make_float2(1.f, 0.f);
            float2* dst = w ? vpw : upw;
            dst[p] = t;
#pragma unroll
            for (int j = 1; j <= 8; j++) { t = cmul(t, u); dst[j*64 + p] = t; }
        }
        __syncthreads();
        // g build: 2 threads per p, 24 slots each (covers 48 slots)
        {
            int p = tid >> 1, part = tid & 1;
#pragma unroll
            for (int n = 0; n < 24; n++) {
                int s = part*24 + n;
                int r = 3*kt + (s >> 4), t = s & 15;
                int ki, mi;
                if (r < 8) { ki = (r == 0) ? 0 : 8 + r; mi = t; }
                else {
                    if (t < 7)       { ki = 1 + t; mi = 0; }
                    else if (t == 7) { ki = 8;     mi = 0; }
                    else             { ki = 8;     mi = t; }
                }
                int kk = ki - 8, mm = mi - 8;
                int ka = kk < 0 ? -kk : kk;
                int ma = mm < 0 ? -mm : mm;
                float2 a  = upw[ka*64 + p]; if (kk < 0) a.y  = -a.y;
                float2 bb = vpw[ma*64 + p]; if (mm < 0) bb.y = -bb.y;
                gs[p*GS_PAD + s] = cmul(a, bb);
            }
        }
        __syncthreads();
        // main: 8 channels x 3 modes per thread, p unrolled by 4 (float4 x)
        for (int p = 0; p < 64; p += 4) {
            float4 xv[8];
#pragma unroll
            for (int i = 0; i < 8; i++)
                xv[i] = *(const float4*)&xs[(c0+i)*68 + p];
#pragma unroll
            for (int pp = 0; pp < 4; pp++) {
                const float2* gp = &gs[(p+pp)*GS_PAD + j0];
                float2 g0 = gp[0], g1 = gp[1], g2 = gp[2];
#pragma unroll
                for (int i = 0; i < 8; i++) {
                    float xvv = (pp == 0) ? xv[i].x : (pp == 1) ? xv[i].y
                              : (pp == 2) ? xv[i].z : xv[i].w;
                    float2 X = make_float2(xvv, xvv);
                    acc[i][0] = ffma2(X, g0, acc[i][0]);
                    acc[i][1] = ffma2(X, g1, acc[i][1]);
                    acc[i][2] = ffma2(X, g2, acc[i][2]);
                }
            }
        }
    }
#pragma unroll
    for (int ci = 0; ci < 8; ci++)
#pragma unroll
        for (int jj = 0; jj < 3; jj++) {
            int j = kt*48 + j0 + jj;
            red_add_f32x2(&g_xhat[(b*NCAN + j)*CC + c0 + ci], acc[ci][jj]);
        }
}

// ---------------- K_mix: channel mix + modulation (f32x2, i-split) ----------
// grid (256 modes, 4 i-splits), block 256 = 64 o x 4 iq. Each thread: 4 i x 4 b,
// weights read once chip-wide as float4 (wx,wy,-wy,wx) -> 2 ffma2 per cmul.
__global__ void __launch_bounds__(256) k_mix() {
    __shared__ float2 xh[4][64];        // [b][i] canonical-remapped for this mode
    __shared__ float2 red[4][4][64];    // [iq][b][o]
    int mode = blockIdx.x;
    int ys = blockIdx.y;                // 0..3
    int tid = threadIdx.x;
    int o = tid & 63, iq = tid >> 6;
    {
        int i = o, bq = iq;
        int ki = mode >> 4, mi = mode & 15;
        bool canon = (mi == 0) || (ki == 0) || (ki >= 9) || (ki == 8 && mi >= 8);
        int js; float cs;
        if (canon) {
            cs = 1.f;
            if (ki == 0)       js = mi;
            else if (ki >= 9)  js = (ki-8)*16 + mi;
            else if (ki <= 7)  js = 128 + (ki-1);
            else               js = (mi == 0) ? 135 : 128 + mi;
        } else {
            cs = -1.f;
            int ki2 = 16 - ki, mi2 = 16 - mi;
            js = (ki2 >= 9) ? (ki2-8)*16 + mi2 : 128 + mi2;
        }
        float2 v = g_xhat[(bq*NCAN + js)*CC + i];
        xh[bq][i] = make_float2(v.x, cs * v.y);
    }
    __syncthreads();
    float2 acc[4];
#pragma unroll
    for (int b = 0; b < 4; b++) acc[b] = make_float2(0.f, 0.f);
    int ibase = ys*16 + iq*4;
#pragma unroll
    for (int ii = 0; ii < 4; ii++) {
        int i = ibase + ii;
        float4 w4 = g_wT4[mode*(CC*CC) + i*CC + o];
        float2 wlo = make_float2(w4.x, w4.y);
        float2 whi = make_float2(w4.z, w4.w);
#pragma unroll
        for (int b = 0; b < 4; b++) {
            float2 xv = xh[b][i];
            acc[b] = ffma2(make_float2(xv.x, xv.x), wlo, acc[b]);
            acc[b] = ffma2(make_float2(xv.y, xv.y), whi, acc[b]);
        }
    }
#pragma unroll
    for (int b = 0; b < 4; b++) red[iq][b][o] = acc[b];
    __syncthreads();
    {
        int b = tid >> 6;
        float2 s = red[0][b][o];
        s.x += red[1][b][o].x; s.y += red[1][b][o].y;
        s.x += red[2][b][o].x; s.y += red[2][b][o].y;
        s.x += red[3][b][o].x; s.y += red[3][b][o].y;
        float2 ph = g_phi[b*NM + mode];
        red_add_f32x2(&g_xhat2[(b*NM + mode)*CC + o], cmul(ph, s));
    }
}

// ---------------- K_inv: inverse NUFFT (144 folded, 2 points x 8 ch/thread) --
struct InvSmem {
    float2 Ys[NCAN][10];     // folded spectral slab, 8 channels (pad 10)
    float2 apw[9][512];      // u-power chain for 512 points
    float2 wcp[CC][4];       // wc packed channel-pairs (8 channels)
    float  gam[8], bet[8], bcs[8];
};
#define INV_SMEM ((int)sizeof(InvSmem))

__global__ void __launch_bounds__(256, 2) k_inv(const float* __restrict__ x,
                                                const float* __restrict__ pos,
                                                const float* __restrict__ wc,
                                                const float* __restrict__ bc,
                                                float* __restrict__ out) {
    extern __shared__ char smraw[];
    InvSmem& S = *reinterpret_cast<InvSmem*>(smraw);
    int b = blockIdx.z, cg = blockIdx.y;
    int p0 = blockIdx.x * 512;
    int tid = threadIdx.x;
    int cbase = cg * 8;

    // folded slab: Y[j] = X2[mode_j] + conj(X2[partner])
    for (int lin = tid; lin < NCAN*8; lin += 256) {
        int j = lin >> 3, c = lin & 7;
        int ki, mi;
        canon_decode(j, ki, mi);
        float2 v = g_xhat2[(b*NM + ki*16 + mi)*CC + cbase + c];
        bool hasp = (ki >= 1) && (mi >= 1) && !(ki == 8 && mi == 8);
        if (hasp) {
            float2 q = g_xhat2[(b*NM + (16-ki)*16 + (16-mi))*CC + cbase + c];
            v.x += q.x;
            v.y -= q.y;
        }
        S.Ys[j][c] = v;
    }
    {
        int i = tid >> 2, cp = tid & 3;
        S.wcp[i][cp] = make_float2(wc[(cbase + 2*cp    )*CC + i],
                                   wc[(cbase + 2*cp + 1)*CC + i]);
    }
    if (tid < 8) {
        S.gam[tid] = g_gb[b*(2*CC) + cbase + tid];
        S.bet[tid] = g_gb[b*(2*CC) + CC + cbase + tid];
        S.bcs[tid] = bc[cbase + tid];
    }
    float2 bp0[9], bp1[9];
    {
        float2 ps = ((const float2*)pos)[b*PP + p0 + tid];
        float s, c;
        __sincosf(TWO_PI * ps.x, &s, &c); float2 u = make_float2(c, s);
        __sincosf(TWO_PI * ps.y, &s, &c); float2 v = make_float2(c, s);
        float2 t = make_float2(1.f, 0.f);
        S.apw[0][tid] = t;
#pragma unroll
        for (int j = 1; j <= 8; j++) { t = cmul(t, u); S.apw[j][tid] = t; }
        bp0[0] = make_float2(1.f, 0.f);
        t = make_float2(1.f, 0.f);
#pragma unroll
        for (int j = 1; j <= 8; j++) { t = cmul(t, v); bp0[j] = t; }

        ps = ((const float2*)pos)[b*PP + p0 + 256 + tid];
        __sincosf(TWO_PI * ps.x, &s, &c); u = make_float2(c, s);
        __sincosf(TWO_PI * ps.y, &s, &c); v = make_float2(c, s);
        t = make_float2(1.f, 0.f);
        S.apw[0][256 + tid] = t;
#pragma unroll
        for (int j = 1; j <= 8; j++) { t = cmul(t, u); S.apw[j][256 + tid] = t; }
        bp1[0] = make_float2(1.f, 0.f);
        t = make_float2(1.f, 0.f);
#pragma unroll
        for (int j = 1; j <= 8; j++) { t = cmul(t, v); bp1[j] = t; }
    }
    __syncthreads();

    float2 acc0[8], acc1[8];
#pragma unroll
    for (int c = 0; c < 8; c++) { acc0[c] = make_float2(0.f, 0.f); acc1[c] = make_float2(0.f, 0.f); }
    float2 accw0[4], accw1[4];
#pragma unroll
    for (int c = 0; c < 4; c++) { accw0[c] = make_float2(0.f, 0.f); accw1[c] = make_float2(0.f, 0.f); }

    // conv: direct LDG (L2-resident), 2 points
#pragma unroll 8
    for (int i = 0; i < CC; i++) {
        const float* xp = &x[(b*CC + i)*PP + p0 + tid];
        float xv0 = __ldg(xp);
        float xv1 = __ldg(xp + 256);
        float2 xa = make_float2(xv0, xv0), xb = make_float2(xv1, xv1);
#pragma unroll
        for (int cp = 0; cp < 4; cp++) {
            float2 w = S.wcp[i][cp];
            accw0[cp] = ffma2(xa, w, accw0[cp]);
            accw1[cp] = ffma2(xb, w, accw1[cp]);
        }
    }

#define INV_BODY(JIDX)                                                         \
    {                                                                          \
        const float4* xp = (const float4*)&S.Ys[(JIDX)][0];                    \
        _Pragma("unroll")                                                      \
        for (int q = 0; q < 4; q++) {                                          \
            float4 xq = xp[q];                                                 \
            float2 ya = make_float2(xq.x, xq.y);                               \
            float2 yb = make_float2(xq.z, xq.w);                               \
            acc0[2*q]   = ffma2(ya, g0, acc0[2*q]);                            \
            acc0[2*q+1] = ffma2(yb, g0, acc0[2*q+1]);                          \
            acc1[2*q]   = ffma2(ya, g1, acc1[2*q]);                            \
            acc1[2*q+1] = ffma2(yb, g1, acc1[2*q+1]);                          \
        }                                                                      \
    }

    // rows 0..7
    for (int r = 0; r < 8; r++) {
        int ja = (r == 0) ? 8 : r;
        float sk = (r == 0) ? -1.f : 1.f;
        float2 av0 = S.apw[ja][tid];
        float2 av1 = S.apw[ja][256 + tid];
        float ax0 = av0.x, ay0 = sk * av0.y;
        float ax1 = av1.x, ay1 = sk * av1.y;
#pragma unroll
        for (int t = 0; t < 16; t++) {
            float2 bv0 = (t < 8) ? make_float2(bp0[8-t].x, -bp0[8-t].y) : bp0[t-8];
            float2 bv1 = (t < 8) ? make_float2(bp1[8-t].x, -bp1[8-t].y) : bp1[t-8];
            float2 g0 = make_float2(ax0*bv0.x - ay0*bv0.y, ax0*bv0.y + ay0*bv0.x);
            float2 g1 = make_float2(ax1*bv1.x - ay1*bv1.y, ax1*bv1.y + ay1*bv1.x);
            INV_BODY(r*16 + t)
        }
    }
    // row 8 (oddballs)
#pragma unroll
    for (int t = 0; t < 16; t++) {
        float2 g0, g1;
        if (t < 7) {
            float2 av0 = S.apw[7-t][tid];
            float2 av1 = S.apw[7-t][256 + tid];
            float ax0 = av0.x, ay0 = -av0.y;
            float ax1 = av1.x, ay1 = -av1.y;
            float2 bv0 = make_float2(bp0[8].x, -bp0[8].y);
            float2 bv1 = make_float2(bp1[8].x, -bp1[8].y);
            g0 = make_float2(ax0*bv0.x - ay0*bv0.y, ax0*bv0.y + ay0*bv0.x);
            g1 = make_float2(ax1*bv1.x - ay1*bv1.y, ax1*bv1.y + ay1*bv1.x);
        } else if (t == 7) {
            g0 = make_float2(bp0[8].x, -bp0[8].y);
            g1 = make_float2(bp1[8].x, -bp1[8].y);
        } else {
            g0 = bp0[t-8];
            g1 = bp1[t-8];
        }
        INV_BODY(128 + t)
    }
#undef INV_BODY

    float inv = 2.0f / (float)PP;
#pragma unroll
    for (int c = 0; c < 8; c++) {
        float cwa = (c & 1) ? accw0[c >> 1].y : accw0[c >> 1].x;
        float cwb = (c & 1) ? accw1[c >> 1].y : accw1[c >> 1].x;
        float gmc = 1.f + S.gam[c], btc = S.bet[c], bcc = S.bcs[c];
        float x1a = (acc0[c].x + acc0[c].y) * inv;
        float x2a = (cwa + bcc) * gmc + btc;
        float sa = x1a + x2a;
        float x1b = (acc1[c].x + acc1[c].y) * inv;
        float x2b = (cwb + bcc) * gmc + btc;
        float sb = x1b + x2b;
        float* op = &out[(b*CC + cbase + c)*PP + p0 + tid];
        op[0]   = sa / (1.f + __expf(-sa));
        op[256] = sb / (1.f + __expf(-sb));
    }
}

// ---------------- launcher ----------------
extern "C" void kernel_launch(void* const* d_in, const int* in_sizes, int n_in,
                              void* d_out, int out_size) {
    (void)in_sizes; (void)n_in; (void)out_size;
    const float* x        = (const float*)d_in[0];
    const float* pos      = (const float*)d_in[1];
    const float* emb      = (const float*)d_in[2];
    const float* w_real   = (const float*)d_in[3];
    const float* w_imag   = (const float*)d_in[4];
    const float* mod_real = (const float*)d_in[5];
    const float* mod_imag = (const float*)d_in[6];
    const float* W1       = (const float*)d_in[7];
    const float* b1       = (const float*)d_in[8];
    const float* W2       = (const float*)d_in[9];
    const float* b2       = (const float*)d_in[10];
    const float* wc       = (const float*)d_in[11];
    const float* bc       = (const float*)d_in[12];
    float* out = (float*)d_out;

    cudaFuncSetAttribute(k_fwd, cudaFuncAttributeMaxDynamicSharedMemorySize, FWD_SMEM);
    cudaFuncSetAttribute(k_inv, cudaFuncAttributeMaxDynamicSharedMemorySize, INV_SMEM);

    k_prep<<<1220, 256>>>(w_real, w_imag, mod_real, mod_imag, emb, W1, b1, W2, b2);
    k_fwd<<<dim3(64, 3, BB), 128, FWD_SMEM>>>(x, pos);
    k_mix<<<dim3(NM, 4), 256>>>();
    k_inv<<<dim3(PP/512, CC/8, BB), 256, INV_SMEM>>>(x, pos, wc, bc, out);
}